// round 9
// baseline (speedup 1.0000x reference)
#include <cuda_runtime.h>
#include <cuda_bf16.h>
#include <cstdint>

// Problem constants
#define NH 16
#define NB 2
#define NS 2048
#define ND 1024
#define HD 64
#define NM (NS*NB)   // 4096 rows

// ---------------------------------------------------------------------------
// Scratch (device globals). Packed bf16 pairs as uint32.
// ---------------------------------------------------------------------------
__device__ uint32_t g_xh0[(size_t)NM*ND/2], g_xl0[(size_t)NM*ND/2];
__device__ uint32_t g_xh1[(size_t)NM*ND/2], g_xl1[(size_t)NM*ND/2];
__device__ uint32_t g_xh2[(size_t)NM*ND/2], g_xl2[(size_t)NM*ND/2];
__device__ uint32_t g_wh0[(size_t)ND*ND/2], g_wl0[(size_t)ND*ND/2];
__device__ uint32_t g_wh1[(size_t)ND*ND/2], g_wl1[(size_t)ND*ND/2];
__device__ uint32_t g_wh2[(size_t)ND*ND/2], g_wl2[(size_t)ND*ND/2];
__device__ uint32_t g_wh3[(size_t)ND*ND/2], g_wl3[(size_t)ND*ND/2];
__device__ uint32_t g_qh[(size_t)NH*NB*NS*HD/2], g_ql[(size_t)NH*NB*NS*HD/2];
__device__ uint32_t g_kh[(size_t)NH*NB*NS*HD/2], g_kl[(size_t)NH*NB*NS*HD/2];
__device__ uint32_t g_vh[(size_t)NH*NB*NS*HD/2], g_vl[(size_t)NH*NB*NS*HD/2];
__device__ uint32_t g_ch[(size_t)NM*ND/2], g_cl[(size_t)NM*ND/2];

// ===========================================================================
// Baseline-PTX helpers (mma.sync/ldmatrix/cp.async: all <= sm_80 features)
// ===========================================================================
__device__ __forceinline__ uint32_t smem_u32(const void* p) {
    uint32_t a;
    asm("{ .reg .u64 t; cvta.to.shared.u64 t, %1; cvt.u32.u64 %0, t; }"
        : "=r"(a) : "l"(p));
    return a;
}
__device__ __forceinline__ void ldsm_x4(uint32_t* r, uint32_t addr) {
    asm volatile("ldmatrix.sync.aligned.m8n8.x4.shared.b16 {%0,%1,%2,%3}, [%4];"
                 : "=r"(r[0]), "=r"(r[1]), "=r"(r[2]), "=r"(r[3]) : "r"(addr));
}
__device__ __forceinline__ void ldsm_x4_t(uint32_t* r, uint32_t addr) {
    asm volatile("ldmatrix.sync.aligned.m8n8.x4.trans.shared.b16 {%0,%1,%2,%3}, [%4];"
                 : "=r"(r[0]), "=r"(r[1]), "=r"(r[2]), "=r"(r[3]) : "r"(addr));
}
__device__ __forceinline__ void mma_bf16(float* c, const uint32_t* a,
                                         uint32_t b0, uint32_t b1) {
    asm volatile("mma.sync.aligned.m16n8k16.row.col.f32.bf16.bf16.f32 "
                 "{%0,%1,%2,%3}, {%4,%5,%6,%7}, {%8,%9}, {%0,%1,%2,%3};"
                 : "+f"(c[0]), "+f"(c[1]), "+f"(c[2]), "+f"(c[3])
                 : "r"(a[0]), "r"(a[1]), "r"(a[2]), "r"(a[3]),
                   "r"(b0), "r"(b1));
}
__device__ __forceinline__ void cp16(uint32_t sdst, const void* gsrc) {
    asm volatile("cp.async.cg.shared.global [%0], [%1], 16;"
                 :: "r"(sdst), "l"(gsrc));
}
__device__ __forceinline__ void cp_commit() {
    asm volatile("cp.async.commit_group;" ::: "memory");
}
__device__ __forceinline__ void cp_wait1() {
    asm volatile("cp.async.wait_group 1;" ::: "memory");
}
__device__ __forceinline__ void cp_wait0() {
    asm volatile("cp.async.wait_group 0;" ::: "memory");
}
__device__ __forceinline__ uint32_t pk2(__nv_bfloat16 a, __nv_bfloat16 b) {
    return (uint32_t)__bfloat16_as_ushort(a) | ((uint32_t)__bfloat16_as_ushort(b) << 16);
}
__device__ __forceinline__ void split2(float x, __nv_bfloat16& h, __nv_bfloat16& l) {
    h = __float2bfloat16_rn(x);
    l = __float2bfloat16_rn(x - __bfloat162float(h));
}
__device__ __forceinline__ void split_pair(float x, float y, uint32_t& h, uint32_t& l) {
    __nv_bfloat16 hx, lx, hy, ly;
    split2(x, hx, lx); split2(y, hy, ly);
    h = pk2(hx, hy); l = pk2(lx, ly);
}

// ===========================================================================
// split_pack7: fp32 -> packed bf16 hi/lo for 3 inputs + 4 weights, one launch
// ===========================================================================
struct SplitArgs {
    const float4* src[7];
    uint2* hi[7];
    uint2* lo[7];
    int n4[7];
};
__global__ __launch_bounds__(256) void split_pack7(SplitArgs a)
{
    const int z = blockIdx.z;
    const float4* __restrict__ s = a.src[z];
    uint2* __restrict__ hi = a.hi[z];
    uint2* __restrict__ lo = a.lo[z];
    const int n = a.n4[z];
    const int stride = gridDim.x * blockDim.x;
    for (int i = blockIdx.x * blockDim.x + threadIdx.x; i < n; i += stride) {
        float4 v = s[i];
        uint32_t h0, l0, h1, l1;
        split_pair(v.x, v.y, h0, l0);
        split_pair(v.z, v.w, h1, l1);
        hi[i] = make_uint2(h0, h1);
        lo[i] = make_uint2(l0, l1);
    }
}

// ===========================================================================
// HMMA GEMM core (pre-split operands, 3-term split, cp.async double buffer)
// CTA tile 128x128, K-step 32. 8 warps: warp_m=wid>>1 (32 rows), warp_n=wid&1.
// MODE 0: fp32 row-major out.  MODE 1: bf16 hi/lo scatter to [h][b][s][dk].
// ===========================================================================
#define BM 128
#define BN 128
#define BK 32
#define LDT 40                 // padded halves per row (80B)
#define G_ARR  (BM*LDT*2)      // 10240 B per array
#define G_STAGE (4*G_ARR)      // 40960 B per stage
#define GEMM_SMEM (2*G_STAGE)  // 81920 B

template<int MODE>
__device__ __forceinline__ void gemm_core(
    char* smem,
    const uint32_t* __restrict__ Ah2, const uint32_t* __restrict__ Al2,
    const uint32_t* __restrict__ Bh2, const uint32_t* __restrict__ Bl2,
    const float* __restrict__ bias, float* __restrict__ dst,
    uint32_t* __restrict__ dsth, uint32_t* __restrict__ dstl,
    int m0, int n0)
{
    const int tid = threadIdx.x;
    const int wid = tid >> 5, lane = tid & 31;
    const int warp_m = wid >> 1, warp_n = wid & 1;
    const uint32_t sbase = smem_u32(smem);

    const uint32_t* Abh = Ah2 + (size_t)m0 * (ND/2);
    const uint32_t* Abl = Al2 + (size_t)m0 * (ND/2);
    const uint32_t* Bbh = Bh2 + (size_t)n0 * (ND/2);
    const uint32_t* Bbl = Bl2 + (size_t)n0 * (ND/2);

    // Copy one K-stage (ks) into smem stage st: per array 512 x 16B chunks
    auto issue_stage = [&](int ks, int st) {
        const uint32_t sb = sbase + st * G_STAGE;
        #pragma unroll
        for (int it = 0; it < 2; it++) {
            const int c = tid + it * 256;
            const int row = c >> 2, col = c & 3;
            const uint32_t so = (uint32_t)(row * 80 + col * 16);
            const size_t gi = (size_t)row * (ND/2) + ks * 16 + col * 4;
            cp16(sb + 0*G_ARR + so, Abh + gi);
            cp16(sb + 1*G_ARR + so, Abl + gi);
            cp16(sb + 2*G_ARR + so, Bbh + gi);
            cp16(sb + 3*G_ARR + so, Bbl + gi);
        }
    };

    float acc[2][8][4];
    #pragma unroll
    for (int i = 0; i < 2; i++)
        #pragma unroll
        for (int j = 0; j < 8; j++)
            #pragma unroll
            for (int q = 0; q < 4; q++) acc[i][j][q] = 0.f;

    issue_stage(0, 0); cp_commit();
    issue_stage(1, 1); cp_commit();

    for (int ks = 0; ks < ND / BK; ks++) {
        if (ks < ND / BK - 1) cp_wait1(); else cp_wait0();
        __syncthreads();

        const uint32_t sb = sbase + (ks & 1) * G_STAGE;
        const uint32_t sAh = sb, sAl = sb + G_ARR;
        const uint32_t sBh = sb + 2*G_ARR, sBl = sb + 3*G_ARR;

        #pragma unroll
        for (int kk = 0; kk < 2; kk++) {
            uint32_t ah[2][4], al[2][4];
            #pragma unroll
            for (int i = 0; i < 2; i++) {
                const uint32_t aoff = (uint32_t)(
                    (warp_m * 32 + i * 16 + (lane & 15)) * LDT
                    + kk * 16 + (lane >> 4) * 8) * 2;
                ldsm_x4(ah[i], sAh + aoff);
                ldsm_x4(al[i], sAl + aoff);
            }
            #pragma unroll
            for (int g = 0; g < 4; g++) {
                uint32_t bh[4], bl[4];
                const uint32_t boff = (uint32_t)(
                    (warp_n * 64 + g * 16 + (lane & 15)) * LDT
                    + kk * 16 + (lane >> 4) * 8) * 2;
                ldsm_x4(bh, sBh + boff);
                ldsm_x4(bl, sBl + boff);
                #pragma unroll
                for (int i = 0; i < 2; i++) {
                    mma_bf16(acc[i][2*g],   ah[i], bh[0], bh[2]);
                    mma_bf16(acc[i][2*g],   ah[i], bl[0], bl[2]);
                    mma_bf16(acc[i][2*g],   al[i], bh[0], bh[2]);
                    mma_bf16(acc[i][2*g+1], ah[i], bh[1], bh[3]);
                    mma_bf16(acc[i][2*g+1], ah[i], bl[1], bl[3]);
                    mma_bf16(acc[i][2*g+1], al[i], bh[1], bh[3]);
                }
            }
        }
        __syncthreads();
        if (ks + 2 < ND / BK) { issue_stage(ks + 2, ks & 1); cp_commit(); }
    }

    // Epilogue
    #pragma unroll
    for (int i = 0; i < 2; i++) {
        #pragma unroll
        for (int j = 0; j < 8; j++) {
            const int rbase = m0 + warp_m * 32 + i * 16 + (lane >> 2);
            const int cbase = n0 + warp_n * 64 + j * 8 + (lane & 3) * 2;
            const float b0 = bias[cbase], b1 = bias[cbase + 1];
            #pragma unroll
            for (int rr = 0; rr < 2; rr++) {
                const int m = rbase + rr * 8;
                const float o0 = acc[i][j][rr * 2 + 0] + b0;
                const float o1 = acc[i][j][rr * 2 + 1] + b1;
                if (MODE == 0) {
                    *(float2*)&dst[(size_t)m * ND + cbase] = make_float2(o0, o1);
                } else {
                    const int hh = cbase >> 6, dd = cbase & 63;
                    const int srow = m >> 1, bi = m & 1;
                    const size_t idx =
                        (((size_t)(hh * NB + bi)) * NS + srow) * (HD/2) + (dd >> 1);
                    uint32_t ph, pl;
                    split_pair(o0, o1, ph, pl);
                    dsth[idx] = ph;
                    dstl[idx] = pl;
                }
            }
        }
    }
}

struct QkvArgs {
    const uint32_t* ah[3]; const uint32_t* al[3];
    const uint32_t* wh[3]; const uint32_t* wl[3];
    const float* bias[3];
    uint32_t* dh[3]; uint32_t* dl[3];
};
__global__ __launch_bounds__(256, 1) void gemm_qkv(QkvArgs a)
{
    extern __shared__ char smem[];
    const int z = blockIdx.z;
    gemm_core<1>(smem, a.ah[z], a.al[z], a.wh[z], a.wl[z], a.bias[z],
                 nullptr, a.dh[z], a.dl[z],
                 blockIdx.y * BM, blockIdx.x * BN);
}
__global__ __launch_bounds__(256, 1) void gemm_out(
    const uint32_t* ah, const uint32_t* al,
    const uint32_t* wh, const uint32_t* wl,
    const float* bias, float* dst)
{
    extern __shared__ char smem[];
    gemm_core<0>(smem, ah, al, wh, wl, bias, dst, nullptr, nullptr,
                 blockIdx.y * BM, blockIdx.x * BN);
}

// ===========================================================================
// HMMA flash attention, cp.async double-buffered K/V tiles.
// Per (h,b): CTA = 128 q-rows, key tiles of 64. 8 warps x m16 q-rows.
// QK: Qh*Kh + Qh*Kl + Ql*Kh.  PV: Ph*Vh + Ph*Vl + Pl*Vh.
// Epilogue writes ctx pre-split (bf16 hi/lo) for the output projection.
// ===========================================================================
#define LDA 72                       // padded halves per row (144B)
#define AQ_H 0
#define AQ_L (128*LDA*2)             // 18432
#define A_ST0 (2*128*LDA*2)          // 36864
#define A_ARR (64*LDA*2)             // 9216
#define A_STAGE (4*A_ARR)            // 36864
#define ATTN_SMEM (A_ST0 + 2*A_STAGE)  // 110592

__global__ __launch_bounds__(256, 1) void attn_hmma()
{
    extern __shared__ char smem[];
    const uint32_t sbase = smem_u32(smem);

    const int hb = blockIdx.y, qt = blockIdx.x;
    const int tid = threadIdx.x, wid = tid >> 5, lane = tid & 31;

    const uint32_t* qhp = g_qh + ((size_t)hb * NS + (size_t)qt * 128) * (HD/2);
    const uint32_t* qlp = g_ql + ((size_t)hb * NS + (size_t)qt * 128) * (HD/2);
    const uint32_t* khp = g_kh + (size_t)hb * NS * (HD/2);
    const uint32_t* klp = g_kl + (size_t)hb * NS * (HD/2);
    const uint32_t* vhp = g_vh + (size_t)hb * NS * (HD/2);
    const uint32_t* vlp = g_vl + (size_t)hb * NS * (HD/2);

    // Copy K/V tile kt into stage st
    auto issue_kv = [&](int kt, int st) {
        const uint32_t sb = sbase + A_ST0 + st * A_STAGE;
        #pragma unroll
        for (int it = 0; it < 2; it++) {
            const int c = tid + it * 256;
            const int row = c >> 3, col = c & 7;
            const uint32_t so = (uint32_t)(row * 144 + col * 16);
            const size_t gi = (size_t)(kt * 64 + row) * (HD/2) + col * 4;
            cp16(sb + 0*A_ARR + so, khp + gi);
            cp16(sb + 1*A_ARR + so, klp + gi);
            cp16(sb + 2*A_ARR + so, vhp + gi);
            cp16(sb + 3*A_ARR + so, vlp + gi);
        }
    };

    // Q tile (persistent) + stage 0, then stage 1
    #pragma unroll
    for (int it = 0; it < 4; it++) {
        const int c = tid + it * 256;
        const int row = c >> 3, col = c & 7;
        const uint32_t so = (uint32_t)(row * 144 + col * 16);
        const size_t gi = (size_t)row * (HD/2) + col * 4;
        cp16(sbase + AQ_H + so, qhp + gi);
        cp16(sbase + AQ_L + so, qlp + gi);
    }
    issue_kv(0, 0); cp_commit();
    issue_kv(1, 1); cp_commit();

    float o[8][4];
    #pragma unroll
    for (int j = 0; j < 8; j++)
        #pragma unroll
        for (int q = 0; q < 4; q++) o[j][q] = 0.f;
    float m0 = -1e30f, m1 = -1e30f, l0 = 0.f, l1 = 0.f;

    for (int kt = 0; kt < NS / 64; kt++) {
        if (kt < NS / 64 - 1) cp_wait1(); else cp_wait0();
        __syncthreads();

        const uint32_t sb = sbase + A_ST0 + (kt & 1) * A_STAGE;
        const uint32_t sKh = sb, sKl = sb + A_ARR;
        const uint32_t sVh = sb + 2*A_ARR, sVl = sb + 3*A_ARR;

        // ---- QK^T ----
        float sc[8][4];
        #pragma unroll
        for (int j = 0; j < 8; j++)
            #pragma unroll
            for (int q = 0; q < 4; q++) sc[j][q] = 0.f;

        #pragma unroll
        for (int kk = 0; kk < 4; kk++) {
            uint32_t aqh[4], aql[4];
            const uint32_t aoff = (uint32_t)(
                (wid * 16 + (lane & 15)) * LDA + kk * 16 + (lane >> 4) * 8) * 2;
            ldsm_x4(aqh, sbase + AQ_H + aoff);
            ldsm_x4(aql, sbase + AQ_L + aoff);
            #pragma unroll
            for (int g = 0; g < 4; g++) {
                uint32_t bh[4], bl[4];
                const uint32_t boff = (uint32_t)(
                    (g * 16 + (lane & 15)) * LDA + kk * 16 + (lane >> 4) * 8) * 2;
                ldsm_x4(bh, sKh + boff);
                ldsm_x4(bl, sKl + boff);
                mma_bf16(sc[2*g],   aqh, bh[0], bh[2]);
                mma_bf16(sc[2*g],   aqh, bl[0], bl[2]);
                mma_bf16(sc[2*g],   aql, bh[0], bh[2]);
                mma_bf16(sc[2*g+1], aqh, bh[1], bh[3]);
                mma_bf16(sc[2*g+1], aqh, bl[1], bl[3]);
                mma_bf16(sc[2*g+1], aql, bh[1], bh[3]);
            }
        }

        // ---- online softmax ----
        float mx0 = -1e30f, mx1 = -1e30f;
        #pragma unroll
        for (int j = 0; j < 8; j++) {
            sc[j][0] *= 0.125f; sc[j][1] *= 0.125f;
            sc[j][2] *= 0.125f; sc[j][3] *= 0.125f;
            mx0 = fmaxf(mx0, fmaxf(sc[j][0], sc[j][1]));
            mx1 = fmaxf(mx1, fmaxf(sc[j][2], sc[j][3]));
        }
        mx0 = fmaxf(mx0, __shfl_xor_sync(0xffffffffu, mx0, 1));
        mx0 = fmaxf(mx0, __shfl_xor_sync(0xffffffffu, mx0, 2));
        mx1 = fmaxf(mx1, __shfl_xor_sync(0xffffffffu, mx1, 1));
        mx1 = fmaxf(mx1, __shfl_xor_sync(0xffffffffu, mx1, 2));
        const float nm0 = fmaxf(m0, mx0), nm1 = fmaxf(m1, mx1);
        const float cr0 = __expf(m0 - nm0), cr1 = __expf(m1 - nm1);
        m0 = nm0; m1 = nm1;
        float s0 = 0.f, s1 = 0.f;
        #pragma unroll
        for (int j = 0; j < 8; j++) {
            sc[j][0] = __expf(sc[j][0] - nm0); s0 += sc[j][0];
            sc[j][1] = __expf(sc[j][1] - nm0); s0 += sc[j][1];
            sc[j][2] = __expf(sc[j][2] - nm1); s1 += sc[j][2];
            sc[j][3] = __expf(sc[j][3] - nm1); s1 += sc[j][3];
        }
        s0 += __shfl_xor_sync(0xffffffffu, s0, 1);
        s0 += __shfl_xor_sync(0xffffffffu, s0, 2);
        s1 += __shfl_xor_sync(0xffffffffu, s1, 1);
        s1 += __shfl_xor_sync(0xffffffffu, s1, 2);
        l0 = l0 * cr0 + s0;
        l1 = l1 * cr1 + s1;
        #pragma unroll
        for (int j = 0; j < 8; j++) {
            o[j][0] *= cr0; o[j][1] *= cr0;
            o[j][2] *= cr1; o[j][3] *= cr1;
        }

        // ---- PV ----
        #pragma unroll
        for (int kk = 0; kk < 4; kk++) {
            uint32_t ph[4], pl[4];
            split_pair(sc[2*kk][0],   sc[2*kk][1],   ph[0], pl[0]);
            split_pair(sc[2*kk][2],   sc[2*kk][3],   ph[1], pl[1]);
            split_pair(sc[2*kk+1][0], sc[2*kk+1][1], ph[2], pl[2]);
            split_pair(sc[2*kk+1][2], sc[2*kk+1][3], ph[3], pl[3]);
            #pragma unroll
            for (int g = 0; g < 4; g++) {
                uint32_t bvh[4], bvl[4];
                const uint32_t voff = (uint32_t)(
                    (kk * 16 + (lane & 7) + ((lane >> 3) & 1) * 8) * LDA
                    + g * 16 + (lane >> 4) * 8) * 2;
                ldsm_x4_t(bvh, sVh + voff);
                ldsm_x4_t(bvl, sVl + voff);
                mma_bf16(o[2*g],   ph, bvh[0], bvh[1]);
                mma_bf16(o[2*g],   ph, bvl[0], bvl[1]);
                mma_bf16(o[2*g],   pl, bvh[0], bvh[1]);
                mma_bf16(o[2*g+1], ph, bvh[2], bvh[3]);
                mma_bf16(o[2*g+1], ph, bvl[2], bvl[3]);
                mma_bf16(o[2*g+1], pl, bvh[2], bvh[3]);
            }
        }
        __syncthreads();
        if (kt + 2 < NS / 64) { issue_kv(kt + 2, kt & 1); cp_commit(); }
    }

    // ---- epilogue: normalize, split, write ctx hi/lo [s*B+b][dmodel/2] ----
    const int hh = hb >> 1, bi = hb & 1;
    const float inv0 = 1.0f / l0, inv1 = 1.0f / l1;
    const int r0 = qt * 128 + wid * 16 + (lane >> 2);
    const int c2 = (lane & 3) * 2;
    #pragma unroll
    for (int j = 0; j < 8; j++) {
        const int d = hh * HD + j * 8 + c2;
        uint32_t ph, pl;
        split_pair(o[j][0] * inv0, o[j][1] * inv0, ph, pl);
        const size_t i0 = ((size_t)r0 * NB + bi) * (ND/2) + (d >> 1);
        g_ch[i0] = ph; g_cl[i0] = pl;
        split_pair(o[j][2] * inv1, o[j][3] * inv1, ph, pl);
        const size_t i1 = ((size_t)(r0 + 8) * NB + bi) * (ND/2) + (d >> 1);
        g_ch[i1] = ph; g_cl[i1] = pl;
    }
}

// ---------------------------------------------------------------------------
extern "C" void kernel_launch(void* const* d_in, const int* in_sizes, int n_in,
                              void* d_out, int out_size)
{
    const float* query = (const float*)d_in[0];
    const float* key_  = (const float*)d_in[1];
    const float* value = (const float*)d_in[2];
    const float* Wq = (const float*)d_in[3];
    const float* bq = (const float*)d_in[4];
    const float* Wk = (const float*)d_in[5];
    const float* bk = (const float*)d_in[6];
    const float* Wv = (const float*)d_in[7];
    const float* bv = (const float*)d_in[8];
    const float* Wo = (const float*)d_in[9];
    const float* bo = (const float*)d_in[10];
    float* out = (float*)d_out;

    uint32_t *xh0, *xl0, *xh1, *xl1, *xh2, *xl2;
    uint32_t *wh0, *wl0, *wh1, *wl1, *wh2, *wl2, *wh3, *wl3;
    uint32_t *qh, *ql, *kh, *kl, *vh, *vl, *ch, *cl;
    cudaGetSymbolAddress((void**)&xh0, g_xh0); cudaGetSymbolAddress((void**)&xl0, g_xl0);
    cudaGetSymbolAddress((void**)&xh1, g_xh1); cudaGetSymbolAddress((void**)&xl1, g_xl1);
    cudaGetSymbolAddress((void**)&xh2, g_xh2); cudaGetSymbolAddress((void**)&xl2, g_xl2);
    cudaGetSymbolAddress((void**)&wh0, g_wh0); cudaGetSymbolAddress((void**)&wl0, g_wl0);
    cudaGetSymbolAddress((void**)&wh1, g_wh1); cudaGetSymbolAddress((void**)&wl1, g_wl1);
    cudaGetSymbolAddress((void**)&wh2, g_wh2); cudaGetSymbolAddress((void**)&wl2, g_wl2);
    cudaGetSymbolAddress((void**)&wh3, g_wh3); cudaGetSymbolAddress((void**)&wl3, g_wl3);
    cudaGetSymbolAddress((void**)&qh, g_qh);   cudaGetSymbolAddress((void**)&ql, g_ql);
    cudaGetSymbolAddress((void**)&kh, g_kh);   cudaGetSymbolAddress((void**)&kl, g_kl);
    cudaGetSymbolAddress((void**)&vh, g_vh);   cudaGetSymbolAddress((void**)&vl, g_vl);
    cudaGetSymbolAddress((void**)&ch, g_ch);   cudaGetSymbolAddress((void**)&cl, g_cl);

    cudaFuncSetAttribute(gemm_qkv,
                         cudaFuncAttributeMaxDynamicSharedMemorySize, GEMM_SMEM);
    cudaFuncSetAttribute(gemm_out,
                         cudaFuncAttributeMaxDynamicSharedMemorySize, GEMM_SMEM);
    cudaFuncSetAttribute(attn_hmma,
                         cudaFuncAttributeMaxDynamicSharedMemorySize, ATTN_SMEM);

    // 1) Split everything (one launch): 3 inputs + 4 weights
    SplitArgs sa;
    const float* srcs[7] = {query, key_, value, Wq, Wk, Wv, Wo};
    uint32_t* his[7] = {xh0, xh1, xh2, wh0, wh1, wh2, wh3};
    uint32_t* los[7] = {xl0, xl1, xl2, wl0, wl1, wl2, wl3};
    for (int z = 0; z < 7; z++) {
        sa.src[z] = (const float4*)srcs[z];
        sa.hi[z] = (uint2*)his[z];
        sa.lo[z] = (uint2*)los[z];
        sa.n4[z] = (z < 3) ? (NM * ND / 4) : (ND * ND / 4);
    }
    split_pack7<<<dim3(512, 1, 7), 256>>>(sa);

    // 2) Q/K/V projections, batched (grid.z = 3)
    QkvArgs qa;
    qa.ah[0] = xh0; qa.al[0] = xl0; qa.wh[0] = wh0; qa.wl[0] = wl0;
    qa.bias[0] = bq; qa.dh[0] = qh; qa.dl[0] = ql;
    qa.ah[1] = xh1; qa.al[1] = xl1; qa.wh[1] = wh1; qa.wl[1] = wl1;
    qa.bias[1] = bk; qa.dh[1] = kh; qa.dl[1] = kl;
    qa.ah[2] = xh2; qa.al[2] = xl2; qa.wh[2] = wh2; qa.wl[2] = wl2;
    qa.bias[2] = bv; qa.dh[2] = vh; qa.dl[2] = vl;
    gemm_qkv<<<dim3(ND / BN, NM / BM, 3), 256, GEMM_SMEM>>>(qa);

    // 3) Attention (emits pre-split ctx)
    attn_hmma<<<dim3(NS / 128, NH * NB), 256, ATTN_SMEM>>>();

    // 4) Output projection
    gemm_out<<<dim3(ND / BN, NM / BM), 256, GEMM_SMEM>>>(ch, cl, wh3, wl3, bo, out);
}